// round 4
// baseline (speedup 1.0000x reference)
#include <cuda_runtime.h>
#include <stdint.h>

// GridGCNNearNeighbors: for each (b, s) centroid, emit the 32 smallest point
// indices with squared distance <= 0.2^2 (reference: mask -> sort ascending
// indices -> take 32  ==  first-32 in-radius indices in index order),
// padding with the first hit (or N if none).
//
// Harness dtype contract: inputs {float32,int32,bf16}; int64 centroids arrive
// as INT32. Output dtype is FLOAT32 (rel_err==1.0 in R3 == int-bits-as-denormal
// signature), so indices are stored as floats (exact for values <= 8192).
// Inputs identified by element count:
//   pos        float32 [8, 8192, 3]  -> 196608 elements (unique)
//   centroids  int32   [8, 2048]     -> 16384 elements (unique)
// Output: float32 [8, 2048, 32]

namespace {
constexpr int Bb = 8;
constexpr int Nn = 8192;
constexpr int Ss = 2048;
constexpr int Kk = 32;
constexpr float THR = 0.04f;  // (float)(0.2**2)
}

__global__ __launch_bounds__(128)
void gridgcn_knn_kernel(const float* __restrict__ pos,
                        const int* __restrict__ centroids,
                        float* __restrict__ out) {
    const int warp_id = (blockIdx.x * blockDim.x + threadIdx.x) >> 5;
    const int lane = threadIdx.x & 31;
    if (warp_id >= Bb * Ss) return;

    const int b = warp_id >> 11;          // / 2048
    const int c = centroids[warp_id] & (Nn - 1);  // no-op mask for valid input
    const float* __restrict__ posb = pos + (size_t)b * Nn * 3;

    // Center coordinates (warp-uniform broadcast load)
    const float cx = posb[c * 3 + 0];
    const float cy = posb[c * 3 + 1];
    const float cz = posb[c * 3 + 2];
    // Same expansion form as reference: ||c||^2 + ||p||^2 - 2 c.p
    const float sc = cx * cx + cy * cy + cz * cz;

    float* __restrict__ o = out + (size_t)warp_id * Kk;

    int have = 0;
    int first_idx = Nn;  // reference pads with N if zero hits

    #pragma unroll 1
    for (int base = 0; base < Nn; base += 32) {
        const int idx = base + lane;
        const float x = posb[idx * 3 + 0];
        const float y = posb[idx * 3 + 1];
        const float z = posb[idx * 3 + 2];
        const float sp = x * x + y * y + z * z;
        const float dt = cx * x + cy * y + cz * z;
        const float d2 = sc + sp - 2.0f * dt;

        const unsigned mask = __ballot_sync(0xffffffffu, d2 <= THR);
        if (mask) {
            if (have == 0) first_idx = base + (__ffs(mask) - 1);
            const int slot = have + __popc(mask & ((1u << lane) - 1u));
            if (((mask >> lane) & 1u) && slot < Kk) o[slot] = (float)idx;
            have += __popc(mask);
            if (have >= Kk) break;
        }
    }

    // Pad tail with group_first (warp-uniform value)
    const float fpad = (float)first_idx;
    for (int i = have + lane; i < Kk; i += 32) o[i] = fpad;
}

extern "C" void kernel_launch(void* const* d_in, const int* in_sizes, int n_in,
                              void* d_out, int out_size) {
    (void)out_size;
    const float* pos = nullptr;
    const int* centroids = nullptr;
    for (int i = 0; i < n_in; i++) {
        if (in_sizes[i] == Bb * Nn * 3)      pos = (const float*)d_in[i];
        else if (in_sizes[i] == Bb * Ss)     centroids = (const int*)d_in[i];
    }
    float* out = (float*)d_out;

    const int total_warps = Bb * Ss;           // 16384
    const int threads = 128;                   // 4 warps/block
    const int blocks = (total_warps * 32) / threads;  // 4096
    gridgcn_knn_kernel<<<blocks, threads>>>(pos, centroids, out);
}

// round 5
// speedup vs baseline: 1.2063x; 1.2063x over previous
#include <cuda_runtime.h>
#include <stdint.h>

// GridGCNNearNeighbors, R5: SoA transpose + 64-points/iter early-exit warp scan.
//
// For each (b, s) centroid, emit the 32 smallest point indices with squared
// distance <= 0.2^2 (reference: mask -> sort ascending indices -> take 32 ==
// first-32 in-radius indices in index order), padding with the first hit.
//
// Inputs identified by element count (harness delivers int64 as int32):
//   pos        float32 [8, 8192, 3]  -> 196608 elements (unique)
//   centroids  int32   [8, 2048]     -> 16384 elements (unique)
// Output: float32 [8, 2048, 32] (indices stored as floats, exact <= 8192)

namespace {
constexpr int Bb = 8;
constexpr int Nn = 8192;
constexpr int Ss = 2048;
constexpr int Kk = 32;
constexpr float THR = 0.04f;  // (float)(0.2**2)
}

// SoA scratch: coalesced coordinate planes (786 KB total, static device mem)
__device__ float g_x[Bb * Nn];
__device__ float g_y[Bb * Nn];
__device__ float g_z[Bb * Nn];

__global__ __launch_bounds__(256)
void soa_transpose_kernel(const float* __restrict__ pos) {
    const int i = blockIdx.x * blockDim.x + threadIdx.x;
    if (i >= Bb * Nn) return;
    const float* p = pos + (size_t)i * 3;
    g_x[i] = p[0];
    g_y[i] = p[1];
    g_z[i] = p[2];
}

__global__ __launch_bounds__(128)
void gridgcn_knn_kernel(const float* __restrict__ pos,
                        const int* __restrict__ centroids,
                        float* __restrict__ out) {
    const int warp_id = (blockIdx.x * blockDim.x + threadIdx.x) >> 5;
    const int lane = threadIdx.x & 31;
    if (warp_id >= Bb * Ss) return;

    const int b = warp_id >> 11;          // / 2048
    const int c = centroids[warp_id] & (Nn - 1);  // no-op mask for valid input
    const int boff = b * Nn;

    // Center coordinates from original AoS pos (warp-uniform broadcast load;
    // identical bits to what the SoA holds)
    const float* posb = pos + (size_t)boff * 3;
    const float cx = posb[c * 3 + 0];
    const float cy = posb[c * 3 + 1];
    const float cz = posb[c * 3 + 2];
    // Same expansion form as reference: ||c||^2 + ||p||^2 - 2 c.p
    const float sc = cx * cx + cy * cy + cz * cz;

    const float* __restrict__ px = g_x + boff;
    const float* __restrict__ py = g_y + boff;
    const float* __restrict__ pz = g_z + boff;

    float* __restrict__ o = out + (size_t)warp_id * Kk;

    int have = 0;
    int first_idx = Nn;  // reference pads with N if zero hits

    #pragma unroll 1
    for (int base = 0; base < Nn; base += 64) {
        const int i0 = base + lane;
        const int i1 = i0 + 32;
        // Six independent coalesced loads -> good MLP, 1 wavefront each
        const float x0 = px[i0], y0 = py[i0], z0 = pz[i0];
        const float x1 = px[i1], y1 = py[i1], z1 = pz[i1];

        const float sp0 = x0 * x0 + y0 * y0 + z0 * z0;
        const float dt0 = cx * x0 + cy * y0 + cz * z0;
        const float d20 = sc + sp0 - 2.0f * dt0;

        const float sp1 = x1 * x1 + y1 * y1 + z1 * z1;
        const float dt1 = cx * x1 + cy * y1 + cz * z1;
        const float d21 = sc + sp1 - 2.0f * dt1;

        const unsigned m0 = __ballot_sync(0xffffffffu, d20 <= THR);
        const unsigned m1 = __ballot_sync(0xffffffffu, d21 <= THR);

        if (m0 | m1) {
            if (have == 0)
                first_idx = m0 ? (base + __ffs(m0) - 1) : (base + 32 + __ffs(m1) - 1);
            const int c0 = __popc(m0);
            const unsigned below = (1u << lane) - 1u;
            // First 32-point group
            {
                const int slot = have + __popc(m0 & below);
                if (((m0 >> lane) & 1u) && slot < Kk) o[slot] = (float)i0;
            }
            // Second 32-point group (offset by c0 hits from the first)
            {
                const int slot = have + c0 + __popc(m1 & below);
                if (((m1 >> lane) & 1u) && slot < Kk) o[slot] = (float)i1;
            }
            have += c0 + __popc(m1);
            if (have >= Kk) break;
        }
    }

    // Pad tail with group_first (warp-uniform value)
    const float fpad = (float)first_idx;
    for (int i = have + lane; i < Kk; i += 32) o[i] = fpad;
}

extern "C" void kernel_launch(void* const* d_in, const int* in_sizes, int n_in,
                              void* d_out, int out_size) {
    (void)out_size;
    const float* pos = nullptr;
    const int* centroids = nullptr;
    for (int i = 0; i < n_in; i++) {
        if (in_sizes[i] == Bb * Nn * 3)      pos = (const float*)d_in[i];
        else if (in_sizes[i] == Bb * Ss)     centroids = (const int*)d_in[i];
    }
    float* out = (float*)d_out;

    soa_transpose_kernel<<<(Bb * Nn + 255) / 256, 256>>>(pos);

    const int total_warps = Bb * Ss;           // 16384
    const int threads = 128;                   // 4 warps/block
    const int blocks = (total_warps * 32) / threads;  // 4096
    gridgcn_knn_kernel<<<blocks, threads>>>(pos, centroids, out);
}

// round 6
// speedup vs baseline: 1.2515x; 1.0375x over previous
#include <cuda_runtime.h>
#include <stdint.h>

// GridGCNNearNeighbors, R6: SoA + 128-points/iter (4 groups) early-exit scan.
//
// For each (b, s) centroid, emit the 32 smallest point indices with squared
// distance <= 0.2^2 (reference: mask -> sort ascending indices -> take 32 ==
// first-32 in-radius indices in index order), padding with the first hit.
//
// Inputs identified by element count (harness delivers int64 as int32):
//   pos        float32 [8, 8192, 3]  -> 196608 elements (unique)
//   centroids  int32   [8, 2048]     -> 16384 elements (unique)
// Output: float32 [8, 2048, 32] (indices stored as floats, exact <= 8192)

namespace {
constexpr int Bb = 8;
constexpr int Nn = 8192;
constexpr int Ss = 2048;
constexpr int Kk = 32;
constexpr float THR = 0.04f;  // (float)(0.2**2)
}

// SoA scratch planes (static device mem; allocation-free contract)
__device__ float g_x[Bb * Nn];
__device__ float g_y[Bb * Nn];
__device__ float g_z[Bb * Nn];

__global__ __launch_bounds__(256)
void soa_transpose_kernel(const float* __restrict__ pos) {
    const int i = blockIdx.x * blockDim.x + threadIdx.x;
    if (i >= Bb * Nn) return;
    const float* p = pos + (size_t)i * 3;
    g_x[i] = p[0];
    g_y[i] = p[1];
    g_z[i] = p[2];
}

__global__ __launch_bounds__(128)
void gridgcn_knn_kernel(const float* __restrict__ pos,
                        const int* __restrict__ centroids,
                        float* __restrict__ out) {
    const int warp_id = (blockIdx.x * blockDim.x + threadIdx.x) >> 5;
    const int lane = threadIdx.x & 31;
    if (warp_id >= Bb * Ss) return;

    const int b = warp_id >> 11;          // / 2048
    const int c = centroids[warp_id] & (Nn - 1);
    const int boff = b * Nn;

    // Center coordinates (warp-uniform broadcast; same bits as SoA planes)
    const float* posb = pos + (size_t)boff * 3;
    const float cx = posb[c * 3 + 0];
    const float cy = posb[c * 3 + 1];
    const float cz = posb[c * 3 + 2];
    // Same expansion form as reference: ||c||^2 + ||p||^2 - 2 c.p
    const float sc = cx * cx + cy * cy + cz * cz;

    const float* __restrict__ px = g_x + boff;
    const float* __restrict__ py = g_y + boff;
    const float* __restrict__ pz = g_z + boff;

    float* __restrict__ o = out + (size_t)warp_id * Kk;

    int have = 0;
    int first_idx = Nn;
    const unsigned below = (1u << lane) - 1u;

    #pragma unroll 1
    for (int base = 0; base < Nn; base += 128) {
        const int i0 = base + lane;
        // 12 independent coalesced loads issued up-front (MLP ~ 12)
        const float x0 = px[i0],      y0 = py[i0],      z0 = pz[i0];
        const float x1 = px[i0 + 32], y1 = py[i0 + 32], z1 = pz[i0 + 32];
        const float x2 = px[i0 + 64], y2 = py[i0 + 64], z2 = pz[i0 + 64];
        const float x3 = px[i0 + 96], y3 = py[i0 + 96], z3 = pz[i0 + 96];

        const float d20 = sc + (x0 * x0 + y0 * y0 + z0 * z0) - 2.0f * (cx * x0 + cy * y0 + cz * z0);
        const float d21 = sc + (x1 * x1 + y1 * y1 + z1 * z1) - 2.0f * (cx * x1 + cy * y1 + cz * z1);
        const float d22 = sc + (x2 * x2 + y2 * y2 + z2 * z2) - 2.0f * (cx * x2 + cy * y2 + cz * z2);
        const float d23 = sc + (x3 * x3 + y3 * y3 + z3 * z3) - 2.0f * (cx * x3 + cy * y3 + cz * z3);

        const unsigned m0 = __ballot_sync(0xffffffffu, d20 <= THR);
        const unsigned m1 = __ballot_sync(0xffffffffu, d21 <= THR);
        const unsigned m2 = __ballot_sync(0xffffffffu, d22 <= THR);
        const unsigned m3 = __ballot_sync(0xffffffffu, d23 <= THR);

        if (m0 | m1 | m2 | m3) {
            if (have == 0) {
                if (m0)      first_idx = base + __ffs(m0) - 1;
                else if (m1) first_idx = base + 32 + __ffs(m1) - 1;
                else if (m2) first_idx = base + 64 + __ffs(m2) - 1;
                else         first_idx = base + 96 + __ffs(m3) - 1;
            }
            int cum = have;
            {
                const int slot = cum + __popc(m0 & below);
                if (((m0 >> lane) & 1u) && slot < Kk) o[slot] = (float)i0;
                cum += __popc(m0);
            }
            {
                const int slot = cum + __popc(m1 & below);
                if (((m1 >> lane) & 1u) && slot < Kk) o[slot] = (float)(i0 + 32);
                cum += __popc(m1);
            }
            {
                const int slot = cum + __popc(m2 & below);
                if (((m2 >> lane) & 1u) && slot < Kk) o[slot] = (float)(i0 + 64);
                cum += __popc(m2);
            }
            {
                const int slot = cum + __popc(m3 & below);
                if (((m3 >> lane) & 1u) && slot < Kk) o[slot] = (float)(i0 + 96);
                cum += __popc(m3);
            }
            have = cum;
            if (have >= Kk) break;
        }
    }

    // Pad tail with group_first (warp-uniform value)
    const float fpad = (float)first_idx;
    for (int i = have + lane; i < Kk; i += 32) o[i] = fpad;
}

extern "C" void kernel_launch(void* const* d_in, const int* in_sizes, int n_in,
                              void* d_out, int out_size) {
    (void)out_size;
    const float* pos = nullptr;
    const int* centroids = nullptr;
    for (int i = 0; i < n_in; i++) {
        if (in_sizes[i] == Bb * Nn * 3)      pos = (const float*)d_in[i];
        else if (in_sizes[i] == Bb * Ss)     centroids = (const int*)d_in[i];
    }
    float* out = (float*)d_out;

    soa_transpose_kernel<<<(Bb * Nn + 255) / 256, 256>>>(pos);

    const int total_warps = Bb * Ss;           // 16384
    const int threads = 128;                   // 4 warps/block
    const int blocks = (total_warps * 32) / threads;  // 4096
    gridgcn_knn_kernel<<<blocks, threads>>>(pos, centroids, out);
}

// round 7
// speedup vs baseline: 1.6841x; 1.3456x over previous
#include <cuda_runtime.h>
#include <stdint.h>

// GridGCNNearNeighbors, R7: SoA float4 loads + software pipelining + 64-thr blocks.
//
// For each (b, s) centroid, emit the 32 smallest point indices with squared
// distance <= 0.2^2 (reference: mask -> sort ascending indices -> take 32 ==
// first-32 in-radius indices in index order), padding with the first hit.
//
// Inputs identified by element count (harness delivers int64 as int32):
//   pos        float32 [8, 8192, 3]  -> 196608 elements (unique)
//   centroids  int32   [8, 2048]     -> 16384 elements (unique)
// Output: float32 [8, 2048, 32] (indices stored as floats, exact <= 8192)

namespace {
constexpr int Bb = 8;
constexpr int Nn = 8192;
constexpr int Ss = 2048;
constexpr int Kk = 32;
constexpr float THR = 0.04f;  // (float)(0.2**2)
}

// SoA scratch planes (static device mem; 16B-aligned for float4 loads)
__device__ __align__(16) float g_x[Bb * Nn];
__device__ __align__(16) float g_y[Bb * Nn];
__device__ __align__(16) float g_z[Bb * Nn];

__global__ __launch_bounds__(256)
void soa_transpose_kernel(const float* __restrict__ pos) {
    const int i = blockIdx.x * blockDim.x + threadIdx.x;
    if (i >= Bb * Nn) return;
    const float* p = pos + (size_t)i * 3;
    g_x[i] = p[0];
    g_y[i] = p[1];
    g_z[i] = p[2];
}

__global__ __launch_bounds__(64)
void gridgcn_knn_kernel(const int* __restrict__ centroids,
                        float* __restrict__ out) {
    const int warp_id = (blockIdx.x << 1) | (threadIdx.x >> 5);
    const int lane = threadIdx.x & 31;
    if (warp_id >= Bb * Ss) return;

    const int b = warp_id >> 11;          // / 2048
    const int c = centroids[warp_id] & (Nn - 1);
    const int boff = b * Nn;

    const float* __restrict__ px = g_x + boff;
    const float* __restrict__ py = g_y + boff;
    const float* __restrict__ pz = g_z + boff;

    // Center coordinates (warp-uniform broadcast; same bits as original pos)
    const float cx = px[c];
    const float cy = py[c];
    const float cz = pz[c];
    // Same expansion form as reference: ||c||^2 + ||p||^2 - 2 c.p
    const float sc = cx * cx + cy * cy + cz * cz;

    const float4* __restrict__ px4 = (const float4*)px;
    const float4* __restrict__ py4 = (const float4*)py;
    const float4* __restrict__ pz4 = (const float4*)pz;

    float* __restrict__ o = out + (size_t)warp_id * Kk;

    int have = 0;
    int first_idx = Nn;
    const unsigned below = (1u << lane) - 1u;
    const unsigned mybit = 1u << lane;

    // Prefetch tile 0: lane handles points base + 4*lane + {0,1,2,3}
    float4 x4 = px4[lane], y4 = py4[lane], z4 = pz4[lane];

    #pragma unroll 1
    for (int base = 0; base < Nn; base += 128) {
        // Prefetch next tile before consuming this one (overlap LDG with ballots)
        float4 nx4, ny4, nz4;
        const int nbase = base + 128;
        if (nbase < Nn) {
            const int q = (nbase >> 2) + lane;
            nx4 = px4[q]; ny4 = py4[q]; nz4 = pz4[q];
        }

        const float d20 = sc + (x4.x * x4.x + y4.x * y4.x + z4.x * z4.x) - 2.0f * (cx * x4.x + cy * y4.x + cz * z4.x);
        const float d21 = sc + (x4.y * x4.y + y4.y * y4.y + z4.y * z4.y) - 2.0f * (cx * x4.y + cy * y4.y + cz * z4.y);
        const float d22 = sc + (x4.z * x4.z + y4.z * y4.z + z4.z * z4.z) - 2.0f * (cx * x4.z + cy * y4.z + cz * z4.z);
        const float d23 = sc + (x4.w * x4.w + y4.w * y4.w + z4.w * z4.w) - 2.0f * (cx * x4.w + cy * y4.w + cz * z4.w);

        // mask_k bit l  <->  point base + 4*l + k  (lane-major index order)
        const unsigned m0 = __ballot_sync(0xffffffffu, d20 <= THR);
        const unsigned m1 = __ballot_sync(0xffffffffu, d21 <= THR);
        const unsigned m2 = __ballot_sync(0xffffffffu, d22 <= THR);
        const unsigned m3 = __ballot_sync(0xffffffffu, d23 <= THR);

        if (m0 | m1 | m2 | m3) {
            if (have == 0) {
                int cand = 0x7fffffff;
                if (m0) cand = min(cand, 4 * (__ffs(m0) - 1) + 0);
                if (m1) cand = min(cand, 4 * (__ffs(m1) - 1) + 1);
                if (m2) cand = min(cand, 4 * (__ffs(m2) - 1) + 2);
                if (m3) cand = min(cand, 4 * (__ffs(m3) - 1) + 3);
                first_idx = base + cand;
            }
            // Hits with point index < (this lane's k=0 point): all k' at lanes < l
            const int pre = __popc(m0 & below) + __popc(m1 & below) +
                            __popc(m2 & below) + __popc(m3 & below);
            const int p0 = base + 4 * lane;
            int s = have + pre;
            if (m0 & mybit) { if (s < Kk) o[s] = (float)(p0 + 0); s++; }
            if (m1 & mybit) { if (s < Kk) o[s] = (float)(p0 + 1); s++; }
            if (m2 & mybit) { if (s < Kk) o[s] = (float)(p0 + 2); s++; }
            if (m3 & mybit) { if (s < Kk) o[s] = (float)(p0 + 3); s++; }

            have += __popc(m0) + __popc(m1) + __popc(m2) + __popc(m3);
            if (have >= Kk) break;
        }
        x4 = nx4; y4 = ny4; z4 = nz4;
    }

    // Pad tail with group_first (warp-uniform value)
    const float fpad = (float)first_idx;
    for (int i = have + lane; i < Kk; i += 32) o[i] = fpad;
}

extern "C" void kernel_launch(void* const* d_in, const int* in_sizes, int n_in,
                              void* d_out, int out_size) {
    (void)out_size;
    const float* pos = nullptr;
    const int* centroids = nullptr;
    for (int i = 0; i < n_in; i++) {
        if (in_sizes[i] == Bb * Nn * 3)      pos = (const float*)d_in[i];
        else if (in_sizes[i] == Bb * Ss)     centroids = (const int*)d_in[i];
    }
    float* out = (float*)d_out;

    soa_transpose_kernel<<<(Bb * Nn + 255) / 256, 256>>>(pos);

    const int total_warps = Bb * Ss;           // 16384
    const int threads = 64;                    // 2 warps/block: less straggler coupling
    const int blocks = total_warps / 2;        // 8192
    gridgcn_knn_kernel<<<blocks, threads>>>(centroids, out);
}